// round 2
// baseline (speedup 1.0000x reference)
#include <cuda_runtime.h>
#include <cstddef>

// Problem constants (fixed by setup_inputs)
#define B_   32
#define CIN  256
#define COUT 512
#define H_   64
#define W_   64
#define HW   (H_*W_)          // 4096
#define GROUPS 9
#define IN_CPG 28             // 252 channels used, 28 per group
#define OUT_CPG 56            // 504 channels, 56 per group; 504..511 -> group 4

// Scratch: s (B,9,H,W) = 4.5 MiB, W_eff (512,9)
__device__ float g_s[B_ * GROUPS * HW];
__device__ float g_we[COUT * GROUPS];

// ---------------------------------------------------------------------------
// Kernel A: W_eff[o,g] = sum of w_pw[o, 56g..56g+55]; g==4 also adds 504..511
// ---------------------------------------------------------------------------
__global__ void shiftconv_weff(const float* __restrict__ w) {
    int t = blockIdx.x * blockDim.x + threadIdx.x;
    if (t >= COUT * GROUPS) return;
    int o = t / GROUPS;
    int g = t % GROUPS;
    const float* row = w + (size_t)o * COUT;
    float sum = 0.f;
#pragma unroll
    for (int k = 0; k < OUT_CPG; k++) sum += row[g * OUT_CPG + k];
    if (g == 4) {
#pragma unroll
        for (int k = 504; k < 512; k++) sum += row[k];
    }
    g_we[t] = sum;
}

// ---------------------------------------------------------------------------
// Kernel B: s[b,g,h,w] = sum_{k<28} x[b, 28g+k, h, w]   (float4 vectorized)
// ---------------------------------------------------------------------------
__global__ void shiftconv_gsum(const float4* __restrict__ x4) {
    int idx = blockIdx.x * blockDim.x + threadIdx.x;     // over B*9*(HW/4)
    const int TOT = B_ * GROUPS * (HW / 4);
    if (idx >= TOT) return;
    int hw4 = idx & (HW / 4 - 1);                        // 0..1023
    int t   = idx >> 10;                                 // b*9+g
    int b = t / GROUPS, g = t % GROUPS;
    const float4* p = x4 + ((size_t)(b * CIN + g * IN_CPG) << 10) + hw4;
    float4 a = make_float4(0.f, 0.f, 0.f, 0.f);
#pragma unroll
    for (int k = 0; k < IN_CPG; k++) {
        float4 v = p[(size_t)k << 10];                   // channel stride = 1024 float4
        a.x += v.x; a.y += v.y; a.z += v.z; a.w += v.w;
    }
    reinterpret_cast<float4*>(g_s)[(size_t)t * (HW / 4) + hw4] = a;
}

// ---------------------------------------------------------------------------
// Kernel C: y[b,o,h,w] = sum_g W_eff[o,g] * s[b,g, h+dy, w+dx]
// Block = (b, 4 h-rows). 256 threads: tx=w (0..63), tg (0..3) -> o quarter.
// Each thread: 9x4 shifted s values in registers, loops 128 o's,
// weights from shared (warp-broadcast LDS), 4 outputs per o.
// ---------------------------------------------------------------------------
#define TH 4
__global__ __launch_bounds__(256) void shiftconv_pw(float* __restrict__ y) {
    __shared__ float w_sh[COUT * GROUPS];                // 18.4 KB

    const int b  = blockIdx.x;                           // 0..31
    const int h0 = blockIdx.y * TH;                      // 0,4,...,60
    const int tid = threadIdx.x;

    for (int i = tid; i < COUT * GROUPS; i += 256)
        w_sh[i] = g_we[i];
    __syncthreads();

    const int tx = tid & 63;                             // w
    const int tg = tid >> 6;                             // 0..3

    // Load shifted s values for this thread's 4 pixels
    float sv[GROUPS][TH];
#pragma unroll
    for (int g = 0; g < GROUPS; g++) {
        const int dy = g / 3 - 1;
        const int dx = g % 3 - 1;
        const int wp = tx + dx;
        const bool wok = (unsigned)wp < (unsigned)W_;
        const float* sg = g_s + (size_t)(b * GROUPS + g) * HW;
#pragma unroll
        for (int r = 0; r < TH; r++) {
            const int hp = h0 + r + dy;
            sv[g][r] = (wok && (unsigned)hp < (unsigned)H_) ? sg[hp * W_ + wp] : 0.f;
        }
    }

    float* yb = y + (size_t)b * COUT * HW + (size_t)h0 * W_ + tx;
    const int o_beg = tg * (COUT / 4);
#pragma unroll 4
    for (int oo = 0; oo < COUT / 4; oo++) {
        const int o = o_beg + oo;
        const float* wo = &w_sh[o * GROUPS];
        float a0 = 0.f, a1 = 0.f, a2 = 0.f, a3 = 0.f;
#pragma unroll
        for (int g = 0; g < GROUPS; g++) {
            const float wv = wo[g];
            a0 = fmaf(wv, sv[g][0], a0);
            a1 = fmaf(wv, sv[g][1], a1);
            a2 = fmaf(wv, sv[g][2], a2);
            a3 = fmaf(wv, sv[g][3], a3);
        }
        float* yo = yb + (size_t)o * HW;
        yo[0]       = a0;
        yo[W_]      = a1;
        yo[2 * W_]  = a2;
        yo[3 * W_]  = a3;
    }
}

// ---------------------------------------------------------------------------
extern "C" void kernel_launch(void* const* d_in, const int* in_sizes, int n_in,
                              void* d_out, int out_size) {
    const float* x = (const float*)d_in[0];
    const float* w = (const float*)d_in[1];
    // Safety: disambiguate by element count if metadata order differs
    if (n_in >= 2 && in_sizes[0] == COUT * COUT) {
        const float* t = x; x = w; w = t;
    }
    float* y = (float*)d_out;

    shiftconv_weff<<<(COUT * GROUPS + 255) / 256, 256>>>(w);

    const int totB = B_ * GROUPS * (HW / 4);
    shiftconv_gsum<<<(totB + 255) / 256, 256>>>((const float4*)x);

    shiftconv_pw<<<dim3(B_, H_ / TH), 256>>>(y);
}